// round 7
// baseline (speedup 1.0000x reference)
#include <cuda_runtime.h>
#include <math.h>

#define BB 16
#define CC 64
#define NN 2000
#define OCC 64
#define NP 2048   // padded size for bitonic sort
#define TILE 128
#define NT 16     // NT*TILE = 2048 >= NN
#define KP 2048   // prefix index space

// ---------------- scratch (no allocations allowed) ----------------
__device__ float  g_h[BB * NN * OCC];    // h[b][n][c]
__device__ float  g_f1[BB * NN];
__device__ float  g_f2[BB * NN];
__device__ float  g_f2s[BB * NP];        // sorted f2 (ascending), padded +inf
__device__ int    g_perm[BB * NP];       // sorted rank -> original j
__device__ float2 g_pre[BB * KP * OCC];  // within-tile excl prefix {S=exp(.01 f2)*h, B=exp(f2)*h}
__device__ float2 g_preZ[BB * KP];       // within-tile excl prefix of weights {S,B}
__device__ float2 g_ts[BB * NT * OCC];   // per-tile sums {S,B}
__device__ float2 g_tsZ[BB * NT];        // per-tile weight sums {S,B}

// ---------------- kernel A: h = x^T W ; f1 = x^T (W a1), f2 = x^T (W a2) ----------------
// grid (25, 16), block 256; 80 n-columns per block; 5n x 4c register tile per thread
__global__ void k_h(const float* __restrict__ inp, const float* __restrict__ W,
                    const float* __restrict__ a) {
    __shared__ float xs[80][CC + 1];     // [nl][k]
    __shared__ float Ws[CC][OCC + 1];    // [k][c]
    __shared__ float as_[128];
    __shared__ float wa1[CC], wa2[CC];
    int b = blockIdx.y;
    int n0 = blockIdx.x * 80;
    int tid = threadIdx.x;

    for (int t = tid; t < CC * OCC; t += 256)
        Ws[t >> 6][t & 63] = W[t];
    for (int t = tid; t < 80 * CC; t += 256) {
        int c = t / 80, nl = t % 80;
        xs[nl][c] = inp[(b * CC + c) * NN + n0 + nl];
    }
    if (tid < 128) as_[tid] = a[tid];
    __syncthreads();

    if (tid < 128) {   // wa1 = W @ a1, wa2 = W @ a2
        int c = tid & 63;
        const float* av = as_ + (tid >> 6) * 64;
        float s = 0.f;
#pragma unroll
        for (int oc = 0; oc < 64; oc++)
            s = fmaf(Ws[c][oc], av[oc], s);
        if (tid < 64) wa1[c] = s; else wa2[c] = s;
    }

    // ---- register-tiled GEMM: thread owns rows nl0..nl0+4, cols c0..c0+3 ----
    {
        int cg = tid & 15, ng = tid >> 4;
        int c0 = cg * 4, nl0 = ng * 5;
        float4 acc0 = make_float4(0.f, 0.f, 0.f, 0.f);
        float4 acc1 = acc0, acc2 = acc0, acc3 = acc0, acc4 = acc0;
#pragma unroll 8
        for (int k = 0; k < CC; k++) {
            float w0 = Ws[k][c0], w1 = Ws[k][c0 + 1], w2 = Ws[k][c0 + 2], w3 = Ws[k][c0 + 3];
            float x0 = xs[nl0][k], x1 = xs[nl0 + 1][k], x2 = xs[nl0 + 2][k],
                  x3 = xs[nl0 + 3][k], x4 = xs[nl0 + 4][k];
            acc0.x = fmaf(x0, w0, acc0.x); acc0.y = fmaf(x0, w1, acc0.y);
            acc0.z = fmaf(x0, w2, acc0.z); acc0.w = fmaf(x0, w3, acc0.w);
            acc1.x = fmaf(x1, w0, acc1.x); acc1.y = fmaf(x1, w1, acc1.y);
            acc1.z = fmaf(x1, w2, acc1.z); acc1.w = fmaf(x1, w3, acc1.w);
            acc2.x = fmaf(x2, w0, acc2.x); acc2.y = fmaf(x2, w1, acc2.y);
            acc2.z = fmaf(x2, w2, acc2.z); acc2.w = fmaf(x2, w3, acc2.w);
            acc3.x = fmaf(x3, w0, acc3.x); acc3.y = fmaf(x3, w1, acc3.y);
            acc3.z = fmaf(x3, w2, acc3.z); acc3.w = fmaf(x3, w3, acc3.w);
            acc4.x = fmaf(x4, w0, acc4.x); acc4.y = fmaf(x4, w1, acc4.y);
            acc4.z = fmaf(x4, w2, acc4.z); acc4.w = fmaf(x4, w3, acc4.w);
        }
        float4* hrow = (float4*)(g_h + (size_t)(b * NN + n0 + nl0) * OCC + c0);
        size_t rs = OCC / 4;
        hrow[0] = acc0; hrow[rs] = acc1; hrow[2 * rs] = acc2;
        hrow[3 * rs] = acc3; hrow[4 * rs] = acc4;
    }
    __syncthreads();

    if (tid < 80) {   // f1/f2 dot products
        float s1 = 0.f, s2 = 0.f;
#pragma unroll
        for (int k = 0; k < CC; k++) {
            float xv = xs[tid][k];
            s1 = fmaf(xv, wa1[k], s1);
            s2 = fmaf(xv, wa2[k], s2);
        }
        g_f1[b * NN + n0 + tid] = s1;
        g_f2[b * NN + n0 + tid] = s2;
    }
}

// ---------------- kernel C: per-batch bitonic sort of f2 (ascending) ----------------
__global__ void k_sort() {
    __shared__ float key[NP];
    __shared__ int   idx[NP];
    int b = blockIdx.x, tid = threadIdx.x;

    for (int i = tid; i < NP; i += 1024) {
        key[i] = (i < NN) ? g_f2[b * NN + i] : __int_as_float(0x7f800000);
        idx[i] = i;
    }
    __syncthreads();

    for (int kk = 2; kk <= NP; kk <<= 1) {
        for (int j = kk >> 1; j > 0; j >>= 1) {
#pragma unroll
            for (int half = 0; half < 2; half++) {
                int i = tid + half * 1024;
                int ixj = i ^ j;
                if (ixj > i) {
                    bool up = ((i & kk) == 0);
                    float ki = key[i], kx = key[ixj];
                    bool sw = up ? (ki > kx) : (ki < kx);
                    if (sw) {
                        key[i] = kx; key[ixj] = ki;
                        int t = idx[i]; idx[i] = idx[ixj]; idx[ixj] = t;
                    }
                }
            }
            __syncthreads();
        }
    }
    for (int i = tid; i < NP; i += 1024) {
        g_f2s[b * NP + i] = key[i];
        g_perm[b * NP + i] = idx[i];
    }
}

// ---------------- kernel D: within-tile exclusive prefixes + tile sums ----------------
// grid (NT, BB), block 256: 4 segments of 32 rows x 64 channels
#define SEG 32
__global__ void k_tile() {
    __shared__ float  hs[TILE][OCC];       // 32 KB
    __shared__ float  wS[TILE], wB[TILE];
    __shared__ int    pidx[TILE];
    __shared__ float2 segsum[4][OCC];
    __shared__ float2 segoff[4][OCC];
    __shared__ float2 segsumZ[4], segoffZ[4];
    int b = blockIdx.y, t = blockIdx.x, tid = threadIdx.x;
    int r0 = t * TILE;

    if (tid < TILE) {
        int gp = r0 + tid;
        if (gp < NN) {
            float f = g_f2s[b * NP + gp];
            wS[tid] = expf(0.01f * f);
            wB[tid] = expf(f);
            pidx[tid] = g_perm[b * NP + gp];
        } else {
            wS[tid] = 0.f; wB[tid] = 0.f; pidx[tid] = 0;
        }
    }
    __syncthreads();
    for (int x = tid; x < TILE * 16; x += 256) {
        int r = x >> 4, q = x & 15;
        reinterpret_cast<float4*>(hs[r])[q] =
            reinterpret_cast<const float4*>(g_h + (size_t)(b * NN + pidx[r]) * OCC)[q];
    }
    __syncthreads();

    int c = tid & 63, seg = tid >> 6;
    int rbeg = seg * SEG;

    // phase 1: per-segment channel sums
    {
        float aS = 0.f, aB = 0.f;
#pragma unroll 4
        for (int r = 0; r < SEG; r++) {
            int gr = rbeg + r;
            float hv = hs[gr][c];
            aS = fmaf(wS[gr], hv, aS);
            aB = fmaf(wB[gr], hv, aB);
        }
        segsum[seg][c] = make_float2(aS, aB);
    }
    if (tid < 4) {   // Z segment sums (4 threads, one warp)
        int rb = tid * SEG;
        float zS = 0.f, zB = 0.f;
#pragma unroll 4
        for (int r = 0; r < SEG; r++) { zS += wS[rb + r]; zB += wB[rb + r]; }
        segsumZ[tid] = make_float2(zS, zB);
    }
    __syncthreads();

    // phase 2: 4-wide exclusive scan of segment sums; write tile totals
    if (tid < 64) {
        float aS = 0.f, aB = 0.f;
#pragma unroll
        for (int s = 0; s < 4; s++) {
            segoff[s][tid] = make_float2(aS, aB);
            float2 v = segsum[s][tid];
            aS += v.x; aB += v.y;
        }
        g_ts[(b * NT + t) * OCC + tid] = make_float2(aS, aB);
    } else if (tid == 64) {
        float zS = 0.f, zB = 0.f;
#pragma unroll
        for (int s = 0; s < 4; s++) {
            segoffZ[s] = make_float2(zS, zB);
            float2 v = segsumZ[s];
            zS += v.x; zB += v.y;
        }
        g_tsZ[b * NT + t] = make_float2(zS, zB);
    }
    __syncthreads();

    // phase 3: re-walk, write rank-level exclusive prefixes (offset + local)
    {
        float2 o = segoff[seg][c];
        float aS = o.x, aB = o.y;
#pragma unroll 4
        for (int r = 0; r < SEG; r++) {
            int gr = rbeg + r;
            g_pre[(size_t)(b * KP + r0 + gr) * OCC + c] = make_float2(aS, aB);
            float hv = hs[gr][c];
            aS = fmaf(wS[gr], hv, aS);
            aB = fmaf(wB[gr], hv, aB);
        }
    }
    if (tid < 4) {
        int rb = tid * SEG;
        float2 o = segoffZ[tid];
        float zS = o.x, zB = o.y;
#pragma unroll 4
        for (int r = 0; r < SEG; r++) {
            g_preZ[b * KP + r0 + rb + r] = make_float2(zS, zB);
            zS += wS[rb + r]; zB += wB[rb + r];
        }
    }
}

// ---------------- kernel E: search + combine + relu + transpose (80 rows / block) ----------------
// grid (25, 16), block (64, 16)
__global__ void k_out(float* __restrict__ out) {
    __shared__ float  fs[NN];
    __shared__ float  sm[80][OCC + 1];
    __shared__ float2 to[NT + 1][OCC];
    __shared__ float  zpreS[NT + 1], zpreB[NT + 1];
    __shared__ int    kks[80];
    __shared__ float  f1s[80];
    __shared__ float4 rinfo[80];          // {A, aa, rden, pad}

    int b = blockIdx.y;
    int i0 = blockIdx.x * 80;
    int c = threadIdx.x, il = threadIdx.y;
    int tid = il * 64 + c;

    for (int x = tid; x < NN; x += 1024)
        fs[x] = g_f2s[b * NP + x];
    if (tid < 80) f1s[tid] = g_f1[b * NN + i0 + tid];

    if (tid >= 128 && tid < 192) {        // per-channel tile-offset prefix
        int ch = tid - 128;
        float aS = 0.f, aB = 0.f;
#pragma unroll
        for (int t2 = 0; t2 < NT; t2++) {
            to[t2][ch] = make_float2(aS, aB);
            float2 v = g_ts[(b * NT + t2) * OCC + ch];
            aS += v.x; aB += v.y;
        }
        to[NT][ch] = make_float2(aS, aB);
    } else if (tid == 192) {              // Z tile-offset prefix
        float aS = 0.f, aB = 0.f;
#pragma unroll
        for (int t2 = 0; t2 < NT; t2++) {
            zpreS[t2] = aS; zpreB[t2] = aB;
            float2 z = g_tsZ[b * NT + t2];
            aS += z.x; aB += z.y;
        }
        zpreS[NT] = aS; zpreB[NT] = aB;
    }
    __syncthreads();

    // per-row stage: search + all row-only math (once per row, not per channel)
    if (tid < 80) {
        float f1v = f1s[tid];
        float th = -f1v;
        int lo = 0, hi = NN;              // lower_bound: first idx with f2 >= -f1
        while (lo < hi) {
            int mid = (lo + hi) >> 1;
            if (fs[mid] < th) lo = mid + 1; else hi = mid;
        }
        int k = lo, t = lo >> 7;
        float2 preZ = g_preZ[b * KP + k];
        float pZS = zpreS[t] + preZ.x;
        float pZB = zpreB[t] + preZ.y;
        float A  = expf(f1v);
        float aa = expf(0.01f * f1v);
        float den = A * (zpreB[NT] - pZB) + aa * pZS;
        kks[tid] = k;
        rinfo[tid] = make_float4(A, aa, 1.f / den, 0.f);
    }
    __syncthreads();

    // combine: channel-only work (lean inner loop)
    {
        float totB = to[NT][c].y;
#pragma unroll
        for (int g = 0; g < 5; g++) {
            int rl = g * 16 + il;
            int k = kks[rl];
            float4 ri = rinfo[rl];
            float2 pre = g_pre[(size_t)(b * KP + k) * OCC + c];
            float2 tov = to[k >> 7][c];
            float pS = tov.x + pre.x;
            float pB = tov.y + pre.y;
            float num = ri.x * (totB - pB) + ri.y * pS;
            sm[rl][c] = fmaxf(num * ri.z, 0.f);
        }
    }
    __syncthreads();

    // transpose-store with incremental index math (one div total)
    {
        int c2 = tid / 80, i2 = tid % 80;
#pragma unroll
        for (int g = 0; g < 5; g++) {
            out[(b * OCC + c2) * NN + i0 + i2] = sm[i2][c2];
            i2 += 64; c2 += 12;            // +1024 = +12*80 + 64
            if (i2 >= 80) { i2 -= 80; c2 += 1; }
        }
    }
}

// ---------------- launch ----------------
extern "C" void kernel_launch(void* const* d_in, const int* in_sizes, int n_in,
                              void* d_out, int out_size) {
    const float* inp = (const float*)d_in[0];   // (16, 64, 2000)
    const float* W   = (const float*)d_in[1];   // (64, 64)
    const float* a   = (const float*)d_in[2];   // (128, 1)
    // d_in[3] = GL : unused (softmax output strictly positive -> adjacency mask is a no-op)
    float* out = (float*)d_out;                 // (16, 64, 2000)

    k_h   <<<dim3(25, BB), 256>>>(inp, W, a);
    k_sort<<<BB, 1024>>>();
    k_tile<<<dim3(NT, BB), 256>>>();
    k_out <<<dim3(25, BB), dim3(64, 16)>>>(out);
}